// round 11
// baseline (speedup 1.0000x reference)
#include <cuda_runtime.h>
#include <cstdint>

#define BATCH 2
#define SEQ 2048
#define HEADS 16
#define DK 64
#define DMODEL 1024
#define NTOK (BATCH*SEQ)   // 4096

// Scratch (allocation-free rule: device globals)
__device__ float g_Q[BATCH*HEADS*SEQ*DK];   // [b,h,s,d]
__device__ float g_K[BATCH*HEADS*SEQ*DK];
__device__ float g_V[BATCH*HEADS*SEQ*DK];
__device__ float g_AT[NTOK*DMODEL];         // tf32-rounded x, later attention out
__device__ float g_Wqkv[3*DMODEL*DMODEL];   // tf32-rounded weights
__device__ float g_Wo[DMODEL*DMODEL];

struct EpiQKV {
  __device__ __forceinline__ void write(int m, int n, float v) const {
    int part = n >> 10;          // 0=q,1=k,2=v
    int w = n & 1023;
    int h = w >> 6, d = w & 63;
    int b = m >> 11, s = m & 2047;
    float* dst = (part == 0) ? g_Q : (part == 1) ? g_K : g_V;
    dst[(((b*HEADS + h)*SEQ) + s)*DK + d] = v;
  }
};

struct EpiOut {
  float* out;
  __device__ __forceinline__ void write(int m, int n, float v) const {
    out[(size_t)m*DMODEL + n] = v;
  }
};

__device__ __forceinline__ uint32_t f2tf32(float f) {
  uint32_t u;
  asm("cvt.rna.tf32.f32 %0, %1;" : "=r"(u) : "f"(f));
  return u;
}

__device__ __forceinline__ float ex2(float x) {
  float y;
  asm("ex2.approx.ftz.f32 %0, %1;" : "=f"(y) : "f"(x));
  return y;
}

__device__ __forceinline__ void mma_tf32(float* c, const uint32_t* a,
                                         uint32_t b0, uint32_t b1) {
  asm volatile(
    "mma.sync.aligned.m16n8k8.row.col.f32.tf32.tf32.f32 "
    "{%0,%1,%2,%3}, {%4,%5,%6,%7}, {%8,%9}, {%0,%1,%2,%3};\n"
    : "+f"(c[0]), "+f"(c[1]), "+f"(c[2]), "+f"(c[3])
    : "r"(a[0]), "r"(a[1]), "r"(a[2]), "r"(a[3]), "r"(b0), "r"(b1));
}

// ============================================================================
// Pre-round fp32 -> tf32 (RNA) in memory. After this, raw bits == tf32.
// ============================================================================
__global__ void preround_kernel(const float4* __restrict__ src,
                                float4* __restrict__ dst, int n4) {
  int i = blockIdx.x * blockDim.x + threadIdx.x;
  if (i < n4) {
    float4 v = src[i];
    v.x = __uint_as_float(f2tf32(v.x));
    v.y = __uint_as_float(f2tf32(v.y));
    v.z = __uint_as_float(f2tf32(v.z));
    v.w = __uint_as_float(f2tf32(v.w));
    dst[i] = v;
  }
}

// ============================================================================
// TF32 tensor-core GEMM: C[m,n] = sum_k A[m,k] * W[n,k]
// A is always g_AT (pre-rounded). Block 128x256, BK=16, 256 threads = 8 warps
// (2m x 4n), warp tile 64x64 = 4x8 m16n8k8 MMAs. No in-loop cvt.
// Double-buffered cp.async dynamic smem, pad-20 rows.
// ============================================================================
#define BK 16
#define PAD 20
#define GEMM_SMEM ((2*128 + 2*256) * PAD * 4)   // 61440 bytes

template<class Epi>
__global__ __launch_bounds__(256)
void mma_gemm(const float* __restrict__ W, int K, Epi epi)
{
  extern __shared__ float sm[];
  float* Asm = sm;                  // [2][128*PAD]
  float* Bsm = sm + 2*128*PAD;      // [2][256*PAD]
  const float* A = (const float*)g_AT;
  const int bm = blockIdx.y * 128, bn = blockIdx.x * 256;
  const int tid = threadIdx.x;
  const int warp = tid >> 5, lane = tid & 31;
  const int wm = warp >> 2, wn = warp & 3;     // warp grid 2m x 4n
  const int gq = lane >> 2, tg = lane & 3;

  float acc[4][8][4];
  #pragma unroll
  for (int i = 0; i < 4; ++i)
    #pragma unroll
    for (int j = 0; j < 8; ++j)
      #pragma unroll
      for (int r = 0; r < 4; ++r) acc[i][j][r] = 0.f;

  auto load_stage = [&](int stage, int k0) {
    float* As = Asm + stage*128*PAD;
    float* Bs = Bsm + stage*256*PAD;
    #pragma unroll
    for (int c = tid; c < 512; c += 256) {
      int row = c >> 2, kc = (c & 3) << 2;
      const float* gA = A + (size_t)(bm + row) * K + k0 + kc;
      uint32_t dA = (uint32_t)__cvta_generic_to_shared(&As[row*PAD + kc]);
      asm volatile("cp.async.cg.shared.global [%0], [%1], 16;\n" :: "r"(dA), "l"(gA));
    }
    #pragma unroll
    for (int c = tid; c < 1024; c += 256) {
      int row = c >> 2, kc = (c & 3) << 2;
      const float* gB = W + (size_t)(bn + row) * K + k0 + kc;
      uint32_t dB = (uint32_t)__cvta_generic_to_shared(&Bs[row*PAD + kc]);
      asm volatile("cp.async.cg.shared.global [%0], [%1], 16;\n" :: "r"(dB), "l"(gB));
    }
    asm volatile("cp.async.commit_group;\n");
  };

  const int nk = K / BK;
  load_stage(0, 0);

  for (int kt = 0; kt < nk; ++kt) {
    const int stage = kt & 1;
    if (kt + 1 < nk) {
      load_stage(stage ^ 1, (kt + 1) * BK);
      asm volatile("cp.async.wait_group 1;\n");
    } else {
      asm volatile("cp.async.wait_group 0;\n");
    }
    __syncthreads();

    const float* Ab = Asm + stage*128*PAD;
    const float* Bb = Bsm + stage*256*PAD;
    #pragma unroll
    for (int ks = 0; ks < 2; ++ks) {
      const int kc = ks*8 + tg;
      uint32_t af[4][4], bf[8][2];
      #pragma unroll
      for (int mt = 0; mt < 4; ++mt) {
        int r0 = wm*64 + mt*16 + gq;
        af[mt][0] = __float_as_uint(Ab[(r0    )*PAD + kc    ]);
        af[mt][1] = __float_as_uint(Ab[(r0 + 8)*PAD + kc    ]);
        af[mt][2] = __float_as_uint(Ab[(r0    )*PAD + kc + 4]);
        af[mt][3] = __float_as_uint(Ab[(r0 + 8)*PAD + kc + 4]);
      }
      #pragma unroll
      for (int nt = 0; nt < 8; ++nt) {
        int n0 = wn*64 + nt*8 + gq;
        bf[nt][0] = __float_as_uint(Bb[n0*PAD + kc    ]);
        bf[nt][1] = __float_as_uint(Bb[n0*PAD + kc + 4]);
      }
      #pragma unroll
      for (int mt = 0; mt < 4; ++mt)
        #pragma unroll
        for (int nt = 0; nt < 8; ++nt)
          mma_tf32(acc[mt][nt], af[mt], bf[nt][0], bf[nt][1]);
    }
    __syncthreads();
  }

  #pragma unroll
  for (int mt = 0; mt < 4; ++mt) {
    int m0 = bm + wm*64 + mt*16 + gq;
    #pragma unroll
    for (int nt = 0; nt < 8; ++nt) {
      int n0 = bn + wn*64 + nt*8 + tg*2;
      epi.write(m0,     n0,     acc[mt][nt][0]);
      epi.write(m0,     n0 + 1, acc[mt][nt][1]);
      epi.write(m0 + 8, n0,     acc[mt][nt][2]);
      epi.write(m0 + 8, n0 + 1, acc[mt][nt][3]);
    }
  }
}

// ============================================================================
// RoPE in-place on g_Q and g_K.
// ============================================================================
__global__ void rope_kernel(const int* __restrict__ pos) {
  int gid = blockIdx.x * blockDim.x + threadIdx.x;
  int lane = gid & 31;
  int rr = gid >> 5;
  if (rr >= 2*BATCH*HEADS*SEQ) return;
  int tensor = rr >> 16;
  int rem = rr & 65535;
  int s = rem & (SEQ-1);
  float* ptr = tensor ? g_K : g_Q;
  float p = (float)pos[s];
  float freq = __powf(10000.0f, -(float)lane / 32.0f);
  float sn, cs;
  sincosf(p * freq, &sn, &cs);
  size_t base = (size_t)rem * 64 + 2*lane;
  float x1 = ptr[base], x2 = ptr[base+1];
  ptr[base]   = x1*cs - x2*sn;
  ptr[base+1] = x1*sn + x2*cs;
}

// ============================================================================
// TF32-MMA causal flash attention (working r7 kernel; epilogue now rounds
// outputs to tf32 so the O-proj GEMM needs no cvt).
// ============================================================================
#define KP 68
#define VP 72
#define STAGE_F (64*KP + 64*VP)
#define CSCALE 0.18033688011112042f   // (1/8) * log2(e)

__global__ __launch_bounds__(256)
void attn_mma_kernel() {
  extern __shared__ float smem[];
  const int bh = blockIdx.y;
  const int qt = blockIdx.x;
  const int qbase = qt * 128;
  const int tid = threadIdx.x;
  const int warp = tid >> 5, lane = tid & 31;
  const int gq = lane >> 2, tg = lane & 3;
  const int wq = warp * 16;

  const float* Kb = g_K + (size_t)bh*SEQ*DK;
  const float* Vb = g_V + (size_t)bh*SEQ*DK;

  uint32_t qaf[8][4];
  {
    const float* Q0 = g_Q + ((size_t)bh*SEQ + qbase + wq + gq) * DK;
    const float* Q1 = Q0 + 8*DK;
    #pragma unroll
    for (int ks = 0; ks < 8; ++ks) {
      int c = ks*8 + tg;
      qaf[ks][0] = f2tf32(Q0[c]);
      qaf[ks][1] = f2tf32(Q1[c]);
      qaf[ks][2] = f2tf32(Q0[c+4]);
      qaf[ks][3] = f2tf32(Q1[c+4]);
    }
  }

  float oacc[8][4];
  #pragma unroll
  for (int nd = 0; nd < 8; ++nd)
    #pragma unroll
    for (int r = 0; r < 4; ++r) oacc[nd][r] = 0.f;
  float m0 = -1e30f, m1 = -1e30f, l0 = 0.f, l1 = 0.f;

  auto load_tile = [&](int stage, int t) {
    float* Ks = smem + stage*STAGE_F;
    float* Vs = Ks + 64*KP;
    const float* Kg = Kb + (size_t)t*64*DK;
    const float* Vg = Vb + (size_t)t*64*DK;
    #pragma unroll
    for (int i = 0; i < 4; ++i) {
      int idx = i*256 + tid;
      int row = idx >> 4, c4 = (idx & 15) << 2;
      uint32_t dK = (uint32_t)__cvta_generic_to_shared(&Ks[row*KP + c4]);
      asm volatile("cp.async.cg.shared.global [%0], [%1], 16;\n"
                   :: "r"(dK), "l"(Kg + row*DK + c4));
      uint32_t dV = (uint32_t)__cvta_generic_to_shared(&Vs[row*VP + c4]);
      asm volatile("cp.async.cg.shared.global [%0], [%1], 16;\n"
                   :: "r"(dV), "l"(Vg + row*DK + c4));
    }
    asm volatile("cp.async.commit_group;\n");
  };

  const int ntiles = qt*2 + 2;
  load_tile(0, 0);

  for (int t = 0; t < ntiles; ++t) {
    if (t + 1 < ntiles) {
      load_tile((t+1) & 1, t+1);
      asm volatile("cp.async.wait_group 1;\n");
    } else {
      asm volatile("cp.async.wait_group 0;\n");
    }
    __syncthreads();

    const float* Ks = smem + (t & 1)*STAGE_F;
    const float* Vs = Ks + 64*KP;

    if (t*64 <= qbase + wq + 15) {
      float sacc[8][4];
      #pragma unroll
      for (int nt = 0; nt < 8; ++nt) {
        #pragma unroll
        for (int r = 0; r < 4; ++r) sacc[nt][r] = 0.f;
        const float* Krow = Ks + (nt*8 + gq)*KP;
        #pragma unroll
        for (int ks = 0; ks < 8; ++ks) {
          uint32_t b0 = f2tf32(Krow[ks*8 + tg]);
          uint32_t b1 = f2tf32(Krow[ks*8 + tg + 4]);
          mma_tf32(sacc[nt], qaf[ks], b0, b1);
        }
      }

      const int r0g = qbase + wq + gq;
      const int r1g = r0g + 8;
      const bool needm = (t*64 + 63 > qbase + wq);
      #pragma unroll
      for (int nt = 0; nt < 8; ++nt) {
        int c0 = t*64 + nt*8 + 2*tg, c1 = c0 + 1;
        float v0 = sacc[nt][0]*CSCALE, v1 = sacc[nt][1]*CSCALE;
        float v2 = sacc[nt][2]*CSCALE, v3 = sacc[nt][3]*CSCALE;
        if (needm) {
          if (c0 > r0g) v0 = -1e30f;
          if (c1 > r0g) v1 = -1e30f;
          if (c0 > r1g) v2 = -1e30f;
          if (c1 > r1g) v3 = -1e30f;
        }
        sacc[nt][0]=v0; sacc[nt][1]=v1; sacc[nt][2]=v2; sacc[nt][3]=v3;
      }

      float mx0 = -1e30f, mx1 = -1e30f;
      #pragma unroll
      for (int nt = 0; nt < 8; ++nt) {
        mx0 = fmaxf(mx0, fmaxf(sacc[nt][0], sacc[nt][1]));
        mx1 = fmaxf(mx1, fmaxf(sacc[nt][2], sacc[nt][3]));
      }
      mx0 = fmaxf(mx0, __shfl_xor_sync(0xffffffffu, mx0, 1));
      mx0 = fmaxf(mx0, __shfl_xor_sync(0xffffffffu, mx0, 2));
      mx1 = fmaxf(mx1, __shfl_xor_sync(0xffffffffu, mx1, 1));
      mx1 = fmaxf(mx1, __shfl_xor_sync(0xffffffffu, mx1, 2));
      float mn0 = fmaxf(m0, mx0), mn1 = fmaxf(m1, mx1);
      float corr0 = ex2(m0 - mn0), corr1 = ex2(m1 - mn1);
      m0 = mn0; m1 = mn1;

      float rs0 = 0.f, rs1 = 0.f;
      #pragma unroll
      for (int nt = 0; nt < 8; ++nt) {
        float p0 = ex2(sacc[nt][0] - m0); sacc[nt][0] = p0; rs0 += p0;
        float p1 = ex2(sacc[nt][1] - m0); sacc[nt][1] = p1; rs0 += p1;
        float p2 = ex2(sacc[nt][2] - m1); sacc[nt][2] = p2; rs1 += p2;
        float p3 = ex2(sacc[nt][3] - m1); sacc[nt][3] = p3; rs1 += p3;
      }
      rs0 += __shfl_xor_sync(0xffffffffu, rs0, 1);
      rs0 += __shfl_xor_sync(0xffffffffu, rs0, 2);
      rs1 += __shfl_xor_sync(0xffffffffu, rs1, 1);
      rs1 += __shfl_xor_sync(0xffffffffu, rs1, 2);
      l0 = l0*corr0 + rs0;
      l1 = l1*corr1 + rs1;

      #pragma unroll
      for (int nd = 0; nd < 8; ++nd) {
        oacc[nd][0] *= corr0; oacc[nd][1] *= corr0;
        oacc[nd][2] *= corr1; oacc[nd][3] *= corr1;
      }

      const int lane_lo = (lane & 28) | (tg >> 1);
      const int lane_hi = lane_lo + 2;
      #pragma unroll
      for (int kk = 0; kk < 8; ++kk) {
        float x0 = __shfl_sync(0xffffffffu, sacc[kk][0], lane_lo);
        float x1 = __shfl_sync(0xffffffffu, sacc[kk][1], lane_lo);
        float x2 = __shfl_sync(0xffffffffu, sacc[kk][2], lane_lo);
        float x3 = __shfl_sync(0xffffffffu, sacc[kk][3], lane_lo);
        float y0 = __shfl_sync(0xffffffffu, sacc[kk][0], lane_hi);
        float y1 = __shfl_sync(0xffffffffu, sacc[kk][1], lane_hi);
        float y2 = __shfl_sync(0xffffffffu, sacc[kk][2], lane_hi);
        float y3 = __shfl_sync(0xffffffffu, sacc[kk][3], lane_hi);
        bool odd = (tg & 1);
        uint32_t paf[4];
        paf[0] = f2tf32(odd ? x1 : x0);
        paf[1] = f2tf32(odd ? x3 : x2);
        paf[2] = f2tf32(odd ? y1 : y0);
        paf[3] = f2tf32(odd ? y3 : y2);
        const float* Vr0 = Vs + (kk*8 + tg)*VP + gq;
        const float* Vr1 = Vs + (kk*8 + tg + 4)*VP + gq;
        #pragma unroll
        for (int nd = 0; nd < 8; ++nd) {
          uint32_t b0 = f2tf32(Vr0[nd*8]);
          uint32_t b1 = f2tf32(Vr1[nd*8]);
          mma_tf32(oacc[nd], paf, b0, b1);
        }
      }
    }
    __syncthreads();
  }

  // epilogue: write [b,s,h*64], rounded to tf32 for the O-proj GEMM
  const int b = bh >> 4, h = bh & 15;
  const float inv0 = 1.0f / l0, inv1 = 1.0f / l1;
  const int q0 = qbase + wq + gq;
  float* o0 = g_AT + ((size_t)(b*SEQ + q0))*DMODEL + h*DK;
  float* o1 = o0 + (size_t)8*DMODEL;
  #pragma unroll
  for (int nd = 0; nd < 8; ++nd) {
    int c = nd*8 + 2*tg;
    float2 w0 = make_float2(__uint_as_float(f2tf32(oacc[nd][0]*inv0)),
                            __uint_as_float(f2tf32(oacc[nd][1]*inv0)));
    float2 w1 = make_float2(__uint_as_float(f2tf32(oacc[nd][2]*inv1)),
                            __uint_as_float(f2tf32(oacc[nd][3]*inv1)));
    *(float2*)(o0 + c) = w0;
    *(float2*)(o1 + c) = w1;
  }
}

extern "C" void kernel_launch(void* const* d_in, const int* in_sizes, int n_in,
                              void* d_out, int out_size) {
  const float* x    = (const float*)d_in[0];
  const int*   pos  = (const int*)d_in[1];      // token_positions (int32)
  const float* wqkv = (const float*)d_in[2];    // [3072, 1024]
  const float* wo   = (const float*)d_in[3];    // [1024, 1024]
  float* out = (float*)d_out;

  float* d_at;   cudaGetSymbolAddress((void**)&d_at,   g_AT);
  float* d_wqkv; cudaGetSymbolAddress((void**)&d_wqkv, g_Wqkv);
  float* d_wo;   cudaGetSymbolAddress((void**)&d_wo,   g_Wo);

  // 0) Pre-round x and weights to tf32 in memory (removes all in-loop cvt)
  {
    int n4 = NTOK*DMODEL/4;
    preround_kernel<<<(n4+255)/256, 256>>>((const float4*)x, (float4*)d_at, n4);
    n4 = 3*DMODEL*DMODEL/4;
    preround_kernel<<<(n4+255)/256, 256>>>((const float4*)wqkv, (float4*)d_wqkv, n4);
    n4 = DMODEL*DMODEL/4;
    preround_kernel<<<(n4+255)/256, 256>>>((const float4*)wo, (float4*)d_wo, n4);
  }

  cudaFuncSetAttribute(mma_gemm<EpiQKV>,
                       cudaFuncAttributeMaxDynamicSharedMemorySize, GEMM_SMEM);
  cudaFuncSetAttribute(mma_gemm<EpiOut>,
                       cudaFuncAttributeMaxDynamicSharedMemorySize, GEMM_SMEM);

  // 1) QKV projection (TF32 MMA, A = rounded x in g_AT)
  dim3 g1((3*DMODEL)/256, NTOK/128);
  mma_gemm<EpiQKV><<<g1, 256, GEMM_SMEM>>>(d_wqkv, DMODEL, EpiQKV{});

  // 2) RoPE in-place on Q and K
  int total = 2*BATCH*HEADS*SEQ*32;
  rope_kernel<<<total/128, 128>>>(pos);

  // 3) Causal flash attention (TF32 MMA); overwrites g_AT with rounded output
  const int smem_bytes = 2 * STAGE_F * (int)sizeof(float);
  cudaFuncSetAttribute(attn_mma_kernel,
                       cudaFuncAttributeMaxDynamicSharedMemorySize, smem_bytes);
  dim3 g2(SEQ/128, BATCH*HEADS);
  attn_mma_kernel<<<g2, 256, smem_bytes>>>();

  // 4) Output projection (TF32 MMA, A = rounded attention out in g_AT)
  dim3 g3(DMODEL/256, NTOK/128);
  mma_gemm<EpiOut><<<g3, 256, GEMM_SMEM>>>(d_wo, DMODEL, EpiOut{out});
}

// round 12
// speedup vs baseline: 1.0038x; 1.0038x over previous
#include <cuda_runtime.h>
#include <cstdint>

#define BATCH 2
#define SEQ 2048
#define HEADS 16
#define DK 64
#define DMODEL 1024
#define NTOK (BATCH*SEQ)   // 4096

// Scratch (allocation-free rule: device globals)
__device__ float g_Q[BATCH*HEADS*SEQ*DK];   // [b,h,s,d]
__device__ float g_K[BATCH*HEADS*SEQ*DK];
__device__ float g_V[BATCH*HEADS*SEQ*DK];
__device__ float g_AT[NTOK*DMODEL];         // tf32-rounded x, later attention out
__device__ float g_Wqkv[3*DMODEL*DMODEL];   // tf32-rounded weights
__device__ float g_Wo[DMODEL*DMODEL];

struct EpiQKV {
  __device__ __forceinline__ void write(int m, int n, float v) const {
    int part = n >> 10;          // 0=q,1=k,2=v
    int w = n & 1023;
    int h = w >> 6, d = w & 63;
    int b = m >> 11, s = m & 2047;
    float* dst = (part == 0) ? g_Q : (part == 1) ? g_K : g_V;
    dst[(((b*HEADS + h)*SEQ) + s)*DK + d] = v;
  }
};

struct EpiOut {
  float* out;
  __device__ __forceinline__ void write(int m, int n, float v) const {
    out[(size_t)m*DMODEL + n] = v;
  }
};

__device__ __forceinline__ uint32_t f2tf32(float f) {
  uint32_t u;
  asm("cvt.rna.tf32.f32 %0, %1;" : "=r"(u) : "f"(f));
  return u;
}

__device__ __forceinline__ float ex2(float x) {
  float y;
  asm("ex2.approx.ftz.f32 %0, %1;" : "=f"(y) : "f"(x));
  return y;
}

__device__ __forceinline__ void mma_tf32(float* c, const uint32_t* a,
                                         uint32_t b0, uint32_t b1) {
  asm volatile(
    "mma.sync.aligned.m16n8k8.row.col.f32.tf32.tf32.f32 "
    "{%0,%1,%2,%3}, {%4,%5,%6,%7}, {%8,%9}, {%0,%1,%2,%3};\n"
    : "+f"(c[0]), "+f"(c[1]), "+f"(c[2]), "+f"(c[3])
    : "r"(a[0]), "r"(a[1]), "r"(a[2]), "r"(a[3]), "r"(b0), "r"(b1));
}

// ============================================================================
// Pre-round fp32 -> tf32 (RNA) in memory. After this, raw bits == tf32.
// ============================================================================
__global__ void preround_kernel(const float4* __restrict__ src,
                                float4* __restrict__ dst, int n4) {
  int i = blockIdx.x * blockDim.x + threadIdx.x;
  if (i < n4) {
    float4 v = src[i];
    v.x = __uint_as_float(f2tf32(v.x));
    v.y = __uint_as_float(f2tf32(v.y));
    v.z = __uint_as_float(f2tf32(v.z));
    v.w = __uint_as_float(f2tf32(v.w));
    dst[i] = v;
  }
}

// ============================================================================
// TF32 tensor-core GEMM: C[m,n] = sum_k A[m,k] * W[n,k]
// A is g_AT (pre-rounded). Block 128x128, BK=16, 256 threads = 8 warps (2x4),
// warp tile 64x32 = 4x4 m16n8k8 MMAs. No in-loop cvt (raw-bit LDS).
// Static smem double buffer, pad-20 rows (regs ~98 -> 2 CTAs/SM).
// ============================================================================
#define BK 16
#define PAD 20

template<class Epi>
__global__ __launch_bounds__(256)
void mma_gemm(const float* __restrict__ W, int K, Epi epi)
{
  __shared__ float As[2][128*PAD];
  __shared__ float Bs[2][128*PAD];
  const float* A = (const float*)g_AT;
  const int bm = blockIdx.y * 128, bn = blockIdx.x * 128;
  const int tid = threadIdx.x;
  const int warp = tid >> 5, lane = tid & 31;
  const int wm = warp >> 2, wn = warp & 3;
  const int gq = lane >> 2, tg = lane & 3;

  float acc[4][4][4];
  #pragma unroll
  for (int i = 0; i < 4; ++i)
    #pragma unroll
    for (int j = 0; j < 4; ++j)
      #pragma unroll
      for (int r = 0; r < 4; ++r) acc[i][j][r] = 0.f;

  auto load_stage = [&](int stage, int k0) {
    #pragma unroll
    for (int c = tid; c < 512; c += 256) {
      int row = c >> 2, kc = (c & 3) << 2;
      const float* gA = A + (size_t)(bm + row) * K + k0 + kc;
      uint32_t dA = (uint32_t)__cvta_generic_to_shared(&As[stage][row*PAD + kc]);
      asm volatile("cp.async.cg.shared.global [%0], [%1], 16;\n" :: "r"(dA), "l"(gA));
      const float* gB = W + (size_t)(bn + row) * K + k0 + kc;
      uint32_t dB = (uint32_t)__cvta_generic_to_shared(&Bs[stage][row*PAD + kc]);
      asm volatile("cp.async.cg.shared.global [%0], [%1], 16;\n" :: "r"(dB), "l"(gB));
    }
    asm volatile("cp.async.commit_group;\n");
  };

  const int nk = K / BK;
  load_stage(0, 0);

  for (int kt = 0; kt < nk; ++kt) {
    const int stage = kt & 1;
    if (kt + 1 < nk) {
      load_stage(stage ^ 1, (kt + 1) * BK);
      asm volatile("cp.async.wait_group 1;\n");
    } else {
      asm volatile("cp.async.wait_group 0;\n");
    }
    __syncthreads();

    const float* Ab = &As[stage][0];
    const float* Bb = &Bs[stage][0];
    #pragma unroll
    for (int ks = 0; ks < 2; ++ks) {
      const int kc = ks*8 + tg;
      uint32_t af[4][4], bf[4][2];
      #pragma unroll
      for (int mt = 0; mt < 4; ++mt) {
        int r0 = wm*64 + mt*16 + gq;
        af[mt][0] = __float_as_uint(Ab[(r0    )*PAD + kc    ]);
        af[mt][1] = __float_as_uint(Ab[(r0 + 8)*PAD + kc    ]);
        af[mt][2] = __float_as_uint(Ab[(r0    )*PAD + kc + 4]);
        af[mt][3] = __float_as_uint(Ab[(r0 + 8)*PAD + kc + 4]);
      }
      #pragma unroll
      for (int nt = 0; nt < 4; ++nt) {
        int n0 = wn*32 + nt*8 + gq;
        bf[nt][0] = __float_as_uint(Bb[n0*PAD + kc    ]);
        bf[nt][1] = __float_as_uint(Bb[n0*PAD + kc + 4]);
      }
      #pragma unroll
      for (int mt = 0; mt < 4; ++mt)
        #pragma unroll
        for (int nt = 0; nt < 4; ++nt)
          mma_tf32(acc[mt][nt], af[mt], bf[nt][0], bf[nt][1]);
    }
    __syncthreads();
  }

  #pragma unroll
  for (int mt = 0; mt < 4; ++mt) {
    int m0 = bm + wm*64 + mt*16 + gq;
    #pragma unroll
    for (int nt = 0; nt < 4; ++nt) {
      int n0 = bn + wn*32 + nt*8 + tg*2;
      epi.write(m0,     n0,     acc[mt][nt][0]);
      epi.write(m0,     n0 + 1, acc[mt][nt][1]);
      epi.write(m0 + 8, n0,     acc[mt][nt][2]);
      epi.write(m0 + 8, n0 + 1, acc[mt][nt][3]);
    }
  }
}

// ============================================================================
// RoPE in-place on g_Q and g_K.
// ============================================================================
__global__ void rope_kernel(const int* __restrict__ pos) {
  int gid = blockIdx.x * blockDim.x + threadIdx.x;
  int lane = gid & 31;
  int rr = gid >> 5;
  if (rr >= 2*BATCH*HEADS*SEQ) return;
  int tensor = rr >> 16;
  int rem = rr & 65535;
  int s = rem & (SEQ-1);
  float* ptr = tensor ? g_K : g_Q;
  float p = (float)pos[s];
  float freq = __powf(10000.0f, -(float)lane / 32.0f);
  float sn, cs;
  sincosf(p * freq, &sn, &cs);
  size_t base = (size_t)rem * 64 + 2*lane;
  float x1 = ptr[base], x2 = ptr[base+1];
  ptr[base]   = x1*cs - x2*sn;
  ptr[base+1] = x1*sn + x2*cs;
}

// ============================================================================
// TF32-MMA causal flash attention (r7 kernel, epilogue rounds to tf32).
// ============================================================================
#define KP 68
#define VP 72
#define STAGE_F (64*KP + 64*VP)
#define CSCALE 0.18033688011112042f   // (1/8) * log2(e)

__global__ __launch_bounds__(256)
void attn_mma_kernel() {
  extern __shared__ float smem[];
  const int bh = blockIdx.y;
  const int qt = blockIdx.x;
  const int qbase = qt * 128;
  const int tid = threadIdx.x;
  const int warp = tid >> 5, lane = tid & 31;
  const int gq = lane >> 2, tg = lane & 3;
  const int wq = warp * 16;

  const float* Kb = g_K + (size_t)bh*SEQ*DK;
  const float* Vb = g_V + (size_t)bh*SEQ*DK;

  uint32_t qaf[8][4];
  {
    const float* Q0 = g_Q + ((size_t)bh*SEQ + qbase + wq + gq) * DK;
    const float* Q1 = Q0 + 8*DK;
    #pragma unroll
    for (int ks = 0; ks < 8; ++ks) {
      int c = ks*8 + tg;
      qaf[ks][0] = f2tf32(Q0[c]);
      qaf[ks][1] = f2tf32(Q1[c]);
      qaf[ks][2] = f2tf32(Q0[c+4]);
      qaf[ks][3] = f2tf32(Q1[c+4]);
    }
  }

  float oacc[8][4];
  #pragma unroll
  for (int nd = 0; nd < 8; ++nd)
    #pragma unroll
    for (int r = 0; r < 4; ++r) oacc[nd][r] = 0.f;
  float m0 = -1e30f, m1 = -1e30f, l0 = 0.f, l1 = 0.f;

  auto load_tile = [&](int stage, int t) {
    float* Ks = smem + stage*STAGE_F;
    float* Vs = Ks + 64*KP;
    const float* Kg = Kb + (size_t)t*64*DK;
    const float* Vg = Vb + (size_t)t*64*DK;
    #pragma unroll
    for (int i = 0; i < 4; ++i) {
      int idx = i*256 + tid;
      int row = idx >> 4, c4 = (idx & 15) << 2;
      uint32_t dK = (uint32_t)__cvta_generic_to_shared(&Ks[row*KP + c4]);
      asm volatile("cp.async.cg.shared.global [%0], [%1], 16;\n"
                   :: "r"(dK), "l"(Kg + row*DK + c4));
      uint32_t dV = (uint32_t)__cvta_generic_to_shared(&Vs[row*VP + c4]);
      asm volatile("cp.async.cg.shared.global [%0], [%1], 16;\n"
                   :: "r"(dV), "l"(Vg + row*DK + c4));
    }
    asm volatile("cp.async.commit_group;\n");
  };

  const int ntiles = qt*2 + 2;
  load_tile(0, 0);

  for (int t = 0; t < ntiles; ++t) {
    if (t + 1 < ntiles) {
      load_tile((t+1) & 1, t+1);
      asm volatile("cp.async.wait_group 1;\n");
    } else {
      asm volatile("cp.async.wait_group 0;\n");
    }
    __syncthreads();

    const float* Ks = smem + (t & 1)*STAGE_F;
    const float* Vs = Ks + 64*KP;

    if (t*64 <= qbase + wq + 15) {
      float sacc[8][4];
      #pragma unroll
      for (int nt = 0; nt < 8; ++nt) {
        #pragma unroll
        for (int r = 0; r < 4; ++r) sacc[nt][r] = 0.f;
        const float* Krow = Ks + (nt*8 + gq)*KP;
        #pragma unroll
        for (int ks = 0; ks < 8; ++ks) {
          uint32_t b0 = f2tf32(Krow[ks*8 + tg]);
          uint32_t b1 = f2tf32(Krow[ks*8 + tg + 4]);
          mma_tf32(sacc[nt], qaf[ks], b0, b1);
        }
      }

      const int r0g = qbase + wq + gq;
      const int r1g = r0g + 8;
      const bool needm = (t*64 + 63 > qbase + wq);
      #pragma unroll
      for (int nt = 0; nt < 8; ++nt) {
        int c0 = t*64 + nt*8 + 2*tg, c1 = c0 + 1;
        float v0 = sacc[nt][0]*CSCALE, v1 = sacc[nt][1]*CSCALE;
        float v2 = sacc[nt][2]*CSCALE, v3 = sacc[nt][3]*CSCALE;
        if (needm) {
          if (c0 > r0g) v0 = -1e30f;
          if (c1 > r0g) v1 = -1e30f;
          if (c0 > r1g) v2 = -1e30f;
          if (c1 > r1g) v3 = -1e30f;
        }
        sacc[nt][0]=v0; sacc[nt][1]=v1; sacc[nt][2]=v2; sacc[nt][3]=v3;
      }

      float mx0 = -1e30f, mx1 = -1e30f;
      #pragma unroll
      for (int nt = 0; nt < 8; ++nt) {
        mx0 = fmaxf(mx0, fmaxf(sacc[nt][0], sacc[nt][1]));
        mx1 = fmaxf(mx1, fmaxf(sacc[nt][2], sacc[nt][3]));
      }
      mx0 = fmaxf(mx0, __shfl_xor_sync(0xffffffffu, mx0, 1));
      mx0 = fmaxf(mx0, __shfl_xor_sync(0xffffffffu, mx0, 2));
      mx1 = fmaxf(mx1, __shfl_xor_sync(0xffffffffu, mx1, 1));
      mx1 = fmaxf(mx1, __shfl_xor_sync(0xffffffffu, mx1, 2));
      float mn0 = fmaxf(m0, mx0), mn1 = fmaxf(m1, mx1);
      float corr0 = ex2(m0 - mn0), corr1 = ex2(m1 - mn1);
      m0 = mn0; m1 = mn1;

      float rs0 = 0.f, rs1 = 0.f;
      #pragma unroll
      for (int nt = 0; nt < 8; ++nt) {
        float p0 = ex2(sacc[nt][0] - m0); sacc[nt][0] = p0; rs0 += p0;
        float p1 = ex2(sacc[nt][1] - m0); sacc[nt][1] = p1; rs0 += p1;
        float p2 = ex2(sacc[nt][2] - m1); sacc[nt][2] = p2; rs1 += p2;
        float p3 = ex2(sacc[nt][3] - m1); sacc[nt][3] = p3; rs1 += p3;
      }
      rs0 += __shfl_xor_sync(0xffffffffu, rs0, 1);
      rs0 += __shfl_xor_sync(0xffffffffu, rs0, 2);
      rs1 += __shfl_xor_sync(0xffffffffu, rs1, 1);
      rs1 += __shfl_xor_sync(0xffffffffu, rs1, 2);
      l0 = l0*corr0 + rs0;
      l1 = l1*corr1 + rs1;

      #pragma unroll
      for (int nd = 0; nd < 8; ++nd) {
        oacc[nd][0] *= corr0; oacc[nd][1] *= corr0;
        oacc[nd][2] *= corr1; oacc[nd][3] *= corr1;
      }

      const int lane_lo = (lane & 28) | (tg >> 1);
      const int lane_hi = lane_lo + 2;
      #pragma unroll
      for (int kk = 0; kk < 8; ++kk) {
        float x0 = __shfl_sync(0xffffffffu, sacc[kk][0], lane_lo);
        float x1 = __shfl_sync(0xffffffffu, sacc[kk][1], lane_lo);
        float x2 = __shfl_sync(0xffffffffu, sacc[kk][2], lane_lo);
        float x3 = __shfl_sync(0xffffffffu, sacc[kk][3], lane_lo);
        float y0 = __shfl_sync(0xffffffffu, sacc[kk][0], lane_hi);
        float y1 = __shfl_sync(0xffffffffu, sacc[kk][1], lane_hi);
        float y2 = __shfl_sync(0xffffffffu, sacc[kk][2], lane_hi);
        float y3 = __shfl_sync(0xffffffffu, sacc[kk][3], lane_hi);
        bool odd = (tg & 1);
        uint32_t paf[4];
        paf[0] = f2tf32(odd ? x1 : x0);
        paf[1] = f2tf32(odd ? x3 : x2);
        paf[2] = f2tf32(odd ? y1 : y0);
        paf[3] = f2tf32(odd ? y3 : y2);
        const float* Vr0 = Vs + (kk*8 + tg)*VP + gq;
        const float* Vr1 = Vs + (kk*8 + tg + 4)*VP + gq;
        #pragma unroll
        for (int nd = 0; nd < 8; ++nd) {
          uint32_t b0 = f2tf32(Vr0[nd*8]);
          uint32_t b1 = f2tf32(Vr1[nd*8]);
          mma_tf32(oacc[nd], paf, b0, b1);
        }
      }
    }
    __syncthreads();
  }

  // epilogue: write [b,s,h*64], rounded to tf32 for the O-proj GEMM
  const int b = bh >> 4, h = bh & 15;
  const float inv0 = 1.0f / l0, inv1 = 1.0f / l1;
  const int q0 = qbase + wq + gq;
  float* o0 = g_AT + ((size_t)(b*SEQ + q0))*DMODEL + h*DK;
  float* o1 = o0 + (size_t)8*DMODEL;
  #pragma unroll
  for (int nd = 0; nd < 8; ++nd) {
    int c = nd*8 + 2*tg;
    float2 w0 = make_float2(__uint_as_float(f2tf32(oacc[nd][0]*inv0)),
                            __uint_as_float(f2tf32(oacc[nd][1]*inv0)));
    float2 w1 = make_float2(__uint_as_float(f2tf32(oacc[nd][2]*inv1)),
                            __uint_as_float(f2tf32(oacc[nd][3]*inv1)));
    *(float2*)(o0 + c) = w0;
    *(float2*)(o1 + c) = w1;
  }
}

extern "C" void kernel_launch(void* const* d_in, const int* in_sizes, int n_in,
                              void* d_out, int out_size) {
  const float* x    = (const float*)d_in[0];
  const int*   pos  = (const int*)d_in[1];      // token_positions (int32)
  const float* wqkv = (const float*)d_in[2];    // [3072, 1024]
  const float* wo   = (const float*)d_in[3];    // [1024, 1024]
  float* out = (float*)d_out;

  float* d_at;   cudaGetSymbolAddress((void**)&d_at,   g_AT);
  float* d_wqkv; cudaGetSymbolAddress((void**)&d_wqkv, g_Wqkv);
  float* d_wo;   cudaGetSymbolAddress((void**)&d_wo,   g_Wo);

  // 0) Pre-round x and weights to tf32 in memory (removes all in-loop cvt)
  {
    int n4 = NTOK*DMODEL/4;
    preround_kernel<<<(n4+255)/256, 256>>>((const float4*)x, (float4*)d_at, n4);
    n4 = 3*DMODEL*DMODEL/4;
    preround_kernel<<<(n4+255)/256, 256>>>((const float4*)wqkv, (float4*)d_wqkv, n4);
    n4 = DMODEL*DMODEL/4;
    preround_kernel<<<(n4+255)/256, 256>>>((const float4*)wo, (float4*)d_wo, n4);
  }

  // 1) QKV projection (TF32 MMA, A = rounded x in g_AT)
  dim3 g1((3*DMODEL)/128, NTOK/128);
  mma_gemm<EpiQKV><<<g1, 256>>>(d_wqkv, DMODEL, EpiQKV{});

  // 2) RoPE in-place on Q and K
  int total = 2*BATCH*HEADS*SEQ*32;
  rope_kernel<<<total/128, 128>>>(pos);

  // 3) Causal flash attention (TF32 MMA); overwrites g_AT with rounded output
  const int smem_bytes = 2 * STAGE_F * (int)sizeof(float);
  cudaFuncSetAttribute(attn_mma_kernel,
                       cudaFuncAttributeMaxDynamicSharedMemorySize, smem_bytes);
  dim3 g2(SEQ/128, BATCH*HEADS);
  attn_mma_kernel<<<g2, 256, smem_bytes>>>();

  // 4) Output projection (TF32 MMA, A = rounded attention out in g_AT)
  dim3 g3(DMODEL/128, NTOK/128);
  mma_gemm<EpiOut><<<g3, 256>>>(d_wo, DMODEL, EpiOut{out});
}

// round 16
// speedup vs baseline: 1.1296x; 1.1253x over previous
#include <cuda_runtime.h>
#include <cstdint>

#define BATCH 2
#define SEQ 2048
#define HEADS 16
#define DK 64
#define DMODEL 1024
#define NTOK (BATCH*SEQ)   // 4096

// Scratch (allocation-free rule: device globals)
__device__ float g_Q[BATCH*HEADS*SEQ*DK];   // [b,h,s,d]  (RoPE already applied)
__device__ float g_K[BATCH*HEADS*SEQ*DK];
__device__ float g_V[BATCH*HEADS*SEQ*DK];
__device__ float g_AT[NTOK*DMODEL];         // attention out, [b,s,h*DK]

__device__ __forceinline__ uint32_t f2tf32(float f) {
  uint32_t u;
  asm("cvt.rna.tf32.f32 %0, %1;" : "=r"(u) : "f"(f));
  return u;
}
__device__ __forceinline__ float ex2(float x) {
  float y;
  asm("ex2.approx.ftz.f32 %0, %1;" : "=f"(y) : "f"(x));
  return y;
}
__device__ __forceinline__ void mma_tf32(float* c, const uint32_t* a,
                                         uint32_t b0, uint32_t b1) {
  asm volatile(
    "mma.sync.aligned.m16n8k8.row.col.f32.tf32.tf32.f32 "
    "{%0,%1,%2,%3}, {%4,%5,%6,%7}, {%8,%9}, {%0,%1,%2,%3};\n"
    : "+f"(c[0]), "+f"(c[1]), "+f"(c[2]), "+f"(c[3])
    : "r"(a[0]), "r"(a[1]), "r"(a[2]), "r"(a[3]), "r"(b0), "r"(b1));
}

// ---------------------------------------------------------------------------
// Epilogues. write2 receives an even column n and the (n, n+1) value pair —
// exactly a RoPE rotation pair for the Q/K parts of the QKV projection.
// ---------------------------------------------------------------------------
struct EpiQKV {
  const int* pos;
  __device__ __forceinline__ void write2(int m, int n, float v0, float v1) const {
    int part = n >> 10;          // 0=q,1=k,2=v
    int w = n & 1023;
    int h = w >> 6, d = w & 63;  // d even
    int b = m >> 11, s = m & 2047;
    float* dst = (part == 0) ? g_Q : (part == 1) ? g_K : g_V;
    size_t base = (((size_t)(b*HEADS + h)*SEQ) + s)*DK + d;
    if (part == 2) {
      *(float2*)&dst[base] = make_float2(v0, v1);
    } else {
      // RoPE: pair index i = d/2, angle = pos[s] * 10000^(-i/32)
      float p = (float)pos[s];
      float freq = __powf(10000.0f, -(float)(d >> 1) / 32.0f);
      float sn, cs;
      sincosf(p * freq, &sn, &cs);
      *(float2*)&dst[base] = make_float2(v0*cs - v1*sn, v0*sn + v1*cs);
    }
  }
};
struct EpiOut {
  float* out;
  __device__ __forceinline__ void write2(int m, int n, float v0, float v1) const {
    *(float2*)&out[(size_t)m*DMODEL + n] = make_float2(v0, v1);
  }
};

// ============================================================================
// TF32 tensor-core GEMM: C[m,n] = sum_k A[m,k] * W[n,k]   (r7 proven config)
// Block tile 128x128, BK=16, 256 threads = 8 warps (2m x 4n),
// warp tile 64x32 = 4x4 m16n8k8 MMAs. Double-buffered cp.async, pad-20.
// ============================================================================
#define BK 16
#define PAD 20

template<bool FROM_GA, class Epi>
__global__ __launch_bounds__(256)
void mma_gemm(const float* __restrict__ Ain, const float* __restrict__ W,
              int K, Epi epi)
{
  __shared__ float As[2][128*PAD];
  __shared__ float Bs[2][128*PAD];
  const float* A = FROM_GA ? (const float*)g_AT : Ain;
  const int bm = blockIdx.y * 128, bn = blockIdx.x * 128;
  const int tid = threadIdx.x;
  const int warp = tid >> 5, lane = tid & 31;
  const int wm = warp >> 2, wn = warp & 3;
  const int gq = lane >> 2, tg = lane & 3;

  float acc[4][4][4];
  #pragma unroll
  for (int i = 0; i < 4; ++i)
    #pragma unroll
    for (int j = 0; j < 4; ++j)
      #pragma unroll
      for (int r = 0; r < 4; ++r) acc[i][j][r] = 0.f;

  auto load_stage = [&](int stage, int k0) {
    #pragma unroll
    for (int c = tid; c < 512; c += 256) {
      int row = c >> 2, kc = (c & 3) << 2;
      const float* gA = A + (size_t)(bm + row) * K + k0 + kc;
      uint32_t dA = (uint32_t)__cvta_generic_to_shared(&As[stage][row*PAD + kc]);
      asm volatile("cp.async.cg.shared.global [%0], [%1], 16;\n" :: "r"(dA), "l"(gA));
      const float* gB = W + (size_t)(bn + row) * K + k0 + kc;
      uint32_t dB = (uint32_t)__cvta_generic_to_shared(&Bs[stage][row*PAD + kc]);
      asm volatile("cp.async.cg.shared.global [%0], [%1], 16;\n" :: "r"(dB), "l"(gB));
    }
    asm volatile("cp.async.commit_group;\n");
  };

  const int nk = K / BK;
  load_stage(0, 0);

  for (int kt = 0; kt < nk; ++kt) {
    const int stage = kt & 1;
    if (kt + 1 < nk) {
      load_stage(stage ^ 1, (kt + 1) * BK);
      asm volatile("cp.async.wait_group 1;\n");
    } else {
      asm volatile("cp.async.wait_group 0;\n");
    }
    __syncthreads();

    const float* Ab = &As[stage][0];
    const float* Bb = &Bs[stage][0];
    #pragma unroll
    for (int ks = 0; ks < 2; ++ks) {
      const int kc = ks*8 + tg;
      uint32_t af[4][4], bf[4][2];
      #pragma unroll
      for (int mt = 0; mt < 4; ++mt) {
        int r0 = wm*64 + mt*16 + gq;
        af[mt][0] = f2tf32(Ab[(r0    )*PAD + kc    ]);
        af[mt][1] = f2tf32(Ab[(r0 + 8)*PAD + kc    ]);
        af[mt][2] = f2tf32(Ab[(r0    )*PAD + kc + 4]);
        af[mt][3] = f2tf32(Ab[(r0 + 8)*PAD + kc + 4]);
      }
      #pragma unroll
      for (int nt = 0; nt < 4; ++nt) {
        int n0 = wn*32 + nt*8 + gq;
        bf[nt][0] = f2tf32(Bb[n0*PAD + kc    ]);
        bf[nt][1] = f2tf32(Bb[n0*PAD + kc + 4]);
      }
      #pragma unroll
      for (int mt = 0; mt < 4; ++mt)
        #pragma unroll
        for (int nt = 0; nt < 4; ++nt)
          mma_tf32(acc[mt][nt], af[mt], bf[nt][0], bf[nt][1]);
    }
    __syncthreads();
  }

  #pragma unroll
  for (int mt = 0; mt < 4; ++mt) {
    int m0 = bm + wm*64 + mt*16 + gq;
    #pragma unroll
    for (int nt = 0; nt < 4; ++nt) {
      int n0 = bn + wn*32 + nt*8 + tg*2;   // even column
      epi.write2(m0,     n0, acc[mt][nt][0], acc[mt][nt][1]);
      epi.write2(m0 + 8, n0, acc[mt][nt][2], acc[mt][nt][3]);
    }
  }
}

// ============================================================================
// TF32-MMA causal flash attention (r7 kernel; qt reversed for load balance).
// ============================================================================
#define KP 68
#define VP 72
#define STAGE_F (64*KP + 64*VP)
#define CSCALE 0.18033688011112042f   // (1/8) * log2(e)

__global__ __launch_bounds__(256)
void attn_mma_kernel() {
  extern __shared__ float smem[];
  const int bh = blockIdx.y;
  const int qt = (gridDim.x - 1) - blockIdx.x;   // heavy tiles first
  const int qbase = qt * 128;
  const int tid = threadIdx.x;
  const int warp = tid >> 5, lane = tid & 31;
  const int gq = lane >> 2, tg = lane & 3;
  const int wq = warp * 16;

  const float* Kb = g_K + (size_t)bh*SEQ*DK;
  const float* Vb = g_V + (size_t)bh*SEQ*DK;

  uint32_t qaf[8][4];
  {
    const float* Q0 = g_Q + ((size_t)bh*SEQ + qbase + wq + gq) * DK;
    const float* Q1 = Q0 + 8*DK;
    #pragma unroll
    for (int ks = 0; ks < 8; ++ks) {
      int c = ks*8 + tg;
      qaf[ks][0] = f2tf32(Q0[c]);
      qaf[ks][1] = f2tf32(Q1[c]);
      qaf[ks][2] = f2tf32(Q0[c+4]);
      qaf[ks][3] = f2tf32(Q1[c+4]);
    }
  }

  float oacc[8][4];
  #pragma unroll
  for (int nd = 0; nd < 8; ++nd)
    #pragma unroll
    for (int r = 0; r < 4; ++r) oacc[nd][r] = 0.f;
  float m0 = -1e30f, m1 = -1e30f, l0 = 0.f, l1 = 0.f;

  auto load_tile = [&](int stage, int t) {
    float* Ks = smem + stage*STAGE_F;
    float* Vs = Ks + 64*KP;
    const float* Kg = Kb + (size_t)t*64*DK;
    const float* Vg = Vb + (size_t)t*64*DK;
    #pragma unroll
    for (int i = 0; i < 4; ++i) {
      int idx = i*256 + tid;
      int row = idx >> 4, c4 = (idx & 15) << 2;
      uint32_t dK = (uint32_t)__cvta_generic_to_shared(&Ks[row*KP + c4]);
      asm volatile("cp.async.cg.shared.global [%0], [%1], 16;\n"
                   :: "r"(dK), "l"(Kg + row*DK + c4));
      uint32_t dV = (uint32_t)__cvta_generic_to_shared(&Vs[row*VP + c4]);
      asm volatile("cp.async.cg.shared.global [%0], [%1], 16;\n"
                   :: "r"(dV), "l"(Vg + row*DK + c4));
    }
    asm volatile("cp.async.commit_group;\n");
  };

  const int ntiles = qt*2 + 2;
  load_tile(0, 0);

  for (int t = 0; t < ntiles; ++t) {
    if (t + 1 < ntiles) {
      load_tile((t+1) & 1, t+1);
      asm volatile("cp.async.wait_group 1;\n");
    } else {
      asm volatile("cp.async.wait_group 0;\n");
    }
    __syncthreads();

    const float* Ks = smem + (t & 1)*STAGE_F;
    const float* Vs = Ks + 64*KP;

    if (t*64 <= qbase + wq + 15) {
      float sacc[8][4];
      #pragma unroll
      for (int nt = 0; nt < 8; ++nt) {
        #pragma unroll
        for (int r = 0; r < 4; ++r) sacc[nt][r] = 0.f;
        const float* Krow = Ks + (nt*8 + gq)*KP;
        #pragma unroll
        for (int ks = 0; ks < 8; ++ks) {
          uint32_t b0 = f2tf32(Krow[ks*8 + tg]);
          uint32_t b1 = f2tf32(Krow[ks*8 + tg + 4]);
          mma_tf32(sacc[nt], qaf[ks], b0, b1);
        }
      }

      const int r0g = qbase + wq + gq;
      const int r1g = r0g + 8;
      const bool needm = (t*64 + 63 > qbase + wq);
      #pragma unroll
      for (int nt = 0; nt < 8; ++nt) {
        int c0 = t*64 + nt*8 + 2*tg, c1 = c0 + 1;
        float v0 = sacc[nt][0]*CSCALE, v1 = sacc[nt][1]*CSCALE;
        float v2 = sacc[nt][2]*CSCALE, v3 = sacc[nt][3]*CSCALE;
        if (needm) {
          if (c0 > r0g) v0 = -1e30f;
          if (c1 > r0g) v1 = -1e30f;
          if (c0 > r1g) v2 = -1e30f;
          if (c1 > r1g) v3 = -1e30f;
        }
        sacc[nt][0]=v0; sacc[nt][1]=v1; sacc[nt][2]=v2; sacc[nt][3]=v3;
      }

      float mx0 = -1e30f, mx1 = -1e30f;
      #pragma unroll
      for (int nt = 0; nt < 8; ++nt) {
        mx0 = fmaxf(mx0, fmaxf(sacc[nt][0], sacc[nt][1]));
        mx1 = fmaxf(mx1, fmaxf(sacc[nt][2], sacc[nt][3]));
      }
      mx0 = fmaxf(mx0, __shfl_xor_sync(0xffffffffu, mx0, 1));
      mx0 = fmaxf(mx0, __shfl_xor_sync(0xffffffffu, mx0, 2));
      mx1 = fmaxf(mx1, __shfl_xor_sync(0xffffffffu, mx1, 1));
      mx1 = fmaxf(mx1, __shfl_xor_sync(0xffffffffu, mx1, 2));
      float mn0 = fmaxf(m0, mx0), mn1 = fmaxf(m1, mx1);
      float corr0 = ex2(m0 - mn0), corr1 = ex2(m1 - mn1);
      m0 = mn0; m1 = mn1;

      float rs0 = 0.f, rs1 = 0.f;
      #pragma unroll
      for (int nt = 0; nt < 8; ++nt) {
        float p0 = ex2(sacc[nt][0] - m0); sacc[nt][0] = p0; rs0 += p0;
        float p1 = ex2(sacc[nt][1] - m0); sacc[nt][1] = p1; rs0 += p1;
        float p2 = ex2(sacc[nt][2] - m1); sacc[nt][2] = p2; rs1 += p2;
        float p3 = ex2(sacc[nt][3] - m1); sacc[nt][3] = p3; rs1 += p3;
      }
      rs0 += __shfl_xor_sync(0xffffffffu, rs0, 1);
      rs0 += __shfl_xor_sync(0xffffffffu, rs0, 2);
      rs1 += __shfl_xor_sync(0xffffffffu, rs1, 1);
      rs1 += __shfl_xor_sync(0xffffffffu, rs1, 2);
      l0 = l0*corr0 + rs0;
      l1 = l1*corr1 + rs1;

      #pragma unroll
      for (int nd = 0; nd < 8; ++nd) {
        oacc[nd][0] *= corr0; oacc[nd][1] *= corr0;
        oacc[nd][2] *= corr1; oacc[nd][3] *= corr1;
      }

      const int lane_lo = (lane & 28) | (tg >> 1);
      const int lane_hi = lane_lo + 2;
      #pragma unroll
      for (int kk = 0; kk < 8; ++kk) {
        float x0 = __shfl_sync(0xffffffffu, sacc[kk][0], lane_lo);
        float x1 = __shfl_sync(0xffffffffu, sacc[kk][1], lane_lo);
        float x2 = __shfl_sync(0xffffffffu, sacc[kk][2], lane_lo);
        float x3 = __shfl_sync(0xffffffffu, sacc[kk][3], lane_lo);
        float y0 = __shfl_sync(0xffffffffu, sacc[kk][0], lane_hi);
        float y1 = __shfl_sync(0xffffffffu, sacc[kk][1], lane_hi);
        float y2 = __shfl_sync(0xffffffffu, sacc[kk][2], lane_hi);
        float y3 = __shfl_sync(0xffffffffu, sacc[kk][3], lane_hi);
        bool odd = (tg & 1);
        uint32_t paf[4];
        paf[0] = f2tf32(odd ? x1 : x0);
        paf[1] = f2tf32(odd ? x3 : x2);
        paf[2] = f2tf32(odd ? y1 : y0);
        paf[3] = f2tf32(odd ? y3 : y2);
        const float* Vr0 = Vs + (kk*8 + tg)*VP + gq;
        const float* Vr1 = Vs + (kk*8 + tg + 4)*VP + gq;
        #pragma unroll
        for (int nd = 0; nd < 8; ++nd) {
          uint32_t b0 = f2tf32(Vr0[nd*8]);
          uint32_t b1 = f2tf32(Vr1[nd*8]);
          mma_tf32(oacc[nd], paf, b0, b1);
        }
      }
    }
    __syncthreads();
  }

  // epilogue: write [b,s,h*64]
  const int b = bh >> 4, h = bh & 15;
  const float inv0 = 1.0f / l0, inv1 = 1.0f / l1;
  const int q0 = qbase + wq + gq;
  float* o0 = g_AT + ((size_t)(b*SEQ + q0))*DMODEL + h*DK;
  float* o1 = o0 + (size_t)8*DMODEL;
  #pragma unroll
  for (int nd = 0; nd < 8; ++nd) {
    int c = nd*8 + 2*tg;
    float2 w0 = make_float2(oacc[nd][0]*inv0, oacc[nd][1]*inv0);
    float2 w1 = make_float2(oacc[nd][2]*inv1, oacc[nd][3]*inv1);
    *(float2*)(o0 + c) = w0;
    *(float2*)(o1 + c) = w1;
  }
}

extern "C" void kernel_launch(void* const* d_in, const int* in_sizes, int n_in,
                              void* d_out, int out_size) {
  const float* x    = (const float*)d_in[0];
  const int*   pos  = (const int*)d_in[1];      // token_positions (int32)
  const float* wqkv = (const float*)d_in[2];    // [3072, 1024]
  const float* wo   = (const float*)d_in[3];    // [1024, 1024]
  float* out = (float*)d_out;

  // 1) QKV projection (TF32 MMA) with fused RoPE, scatter into head-major Q/K/V
  dim3 g1((3*DMODEL)/128, NTOK/128);
  mma_gemm<false, EpiQKV><<<g1, 256>>>(x, wqkv, DMODEL, EpiQKV{pos});

  // 2) Causal flash attention (TF32 MMA), heavy q-tiles scheduled first
  const int smem_bytes = 2 * STAGE_F * (int)sizeof(float);
  cudaFuncSetAttribute(attn_mma_kernel,
                       cudaFuncAttributeMaxDynamicSharedMemorySize, smem_bytes);
  dim3 g2(SEQ/128, BATCH*HEADS);
  attn_mma_kernel<<<g2, 256, smem_bytes>>>();

  // 3) Output projection (TF32 MMA)
  dim3 g3(DMODEL/128, NTOK/128);
  mma_gemm<true, EpiOut><<<g3, 256>>>(nullptr, wo, DMODEL, EpiOut{out});
}